// round 2
// baseline (speedup 1.0000x reference)
#include <cuda_runtime.h>
#include <cstdint>
#include <cstddef>

#define NN 16384          // nodes
#define KD 512            // in_dim
#define ED 256            // embed_dim
#define BR 32             // rows per CTA
#define NITER 64          // main-loop iterations
#define KC 8              // GEMM k per iteration
#define AC 256            // adj columns per iteration
#define NT 512            // threads per CTA
#define WSP 9             // ws row stride (words), odd -> conflict-free

// shared memory layout (bytes)
#define OFF_ADJ   0u
#define ADJ_STAGE 32768u          // 32 rows * 256 floats
#define OFF_X     65536u          // 32 rows * 512 floats = 65536 B
#define OFF_W     131072u         // 2 * 256*9 floats = 18432 B
#define W_STAGE   (ED * WSP * 4)  // 9216 B
#define OFF_D     149504u         // 32 floats
#define OFF_MB    149632u         // 3 mbarriers
#define SMEM_BYTES 149664

typedef unsigned long long ull;

__device__ __forceinline__ ull pk2(float lo, float hi) {
    ull r; asm("mov.b64 %0, {%1, %2};" : "=l"(r) : "f"(lo), "f"(hi)); return r;
}
__device__ __forceinline__ void upk2(ull v, float& lo, float& hi) {
    asm("mov.b64 {%0, %1}, %2;" : "=f"(lo), "=f"(hi) : "l"(v));
}
__device__ __forceinline__ ull fma2(ull a, ull b, ull c) {
    ull d; asm("fma.rn.f32x2 %0, %1, %2, %3;" : "=l"(d) : "l"(a), "l"(b), "l"(c));
    return d;
}
__device__ __forceinline__ uint32_t s2u(const void* p) {
    uint32_t a;
    asm("{ .reg .u64 t; cvta.to.shared.u64 t, %1; cvt.u32.u64 %0, t; }"
        : "=r"(a) : "l"(p));
    return a;
}
__device__ __forceinline__ void mbar_init(uint32_t mb, uint32_t cnt) {
    asm volatile("mbarrier.init.shared.b64 [%0], %1;" :: "r"(mb), "r"(cnt) : "memory");
}
__device__ __forceinline__ void mbar_expect(uint32_t mb, uint32_t bytes) {
    asm volatile("mbarrier.arrive.expect_tx.shared.b64 _, [%0], %1;"
                 :: "r"(mb), "r"(bytes) : "memory");
}
__device__ __forceinline__ void mbar_wait(uint32_t mb, uint32_t ph) {
    asm volatile(
        "{\n\t.reg .pred P;\n\t"
        "WL%=:\n\t"
        "mbarrier.try_wait.parity.acquire.cta.shared::cta.b64 P, [%0], %1, 0x989680;\n\t"
        "@P bra WD%=;\n\t"
        "bra WL%=;\n\t"
        "WD%=:\n\t}"
        :: "r"(mb), "r"(ph) : "memory");
}
__device__ __forceinline__ void bulk_g2s(uint32_t dst, const void* src,
                                         uint32_t bytes, uint32_t mb) {
    asm volatile(
        "cp.async.bulk.shared::cta.global.mbarrier::complete_tx::bytes [%0], [%1], %2, [%3];"
        :: "r"(dst), "l"(src), "r"(bytes), "r"(mb) : "memory");
}

extern __shared__ char smemc[];

__global__ void __launch_bounds__(NT, 1)
fused_gcn_tma(const float* __restrict__ adj,
              const float* __restrict__ x,
              const float* __restrict__ W,
              float* __restrict__ out)
{
    const int tid  = threadIdx.x;
    const int wid  = tid >> 5;
    const int lane = tid & 31;
    const int rg   = wid & 3;     // row-group: rows 8*rg .. 8*rg+7
    const int eg   = wid >> 2;    // e-group:   cols 64*eg + lane (+32)
    const int r0   = blockIdx.x * BR;

    const uint32_t sb       = s2u(smemc);
    const uint32_t mb_full0 = sb + OFF_MB;
    const uint32_t mb_full1 = sb + OFF_MB + 8;
    const uint32_t mb_x     = sb + OFF_MB + 16;

    if (tid == 0) {
        mbar_init(mb_full0, 1);
        mbar_init(mb_full1, 1);
        mbar_init(mb_x, 1);
    }
    __syncthreads();

    // ---- prologue: x preload (one 64KB bulk), adj stage 0 (32 x 1KB bulks)
    if (tid == 0) {
        mbar_expect(mb_x, BR * KD * 4);
        bulk_g2s(sb + OFF_X, x + (size_t)r0 * KD, BR * KD * 4, mb_x);

        mbar_expect(mb_full0, BR * AC * 4);
        const float* srcA = adj + (size_t)r0 * NN;
        #pragma unroll 4
        for (int r = 0; r < BR; ++r)
            bulk_g2s(sb + OFF_ADJ + r * (AC * 4), srcA + (size_t)r * NN,
                     AC * 4, mb_full0);
    }

    // ---- W prefetch (chunk 0) into registers
    const int we = tid >> 1, wh = tid & 1;
    const float* wsrc = W + (size_t)we * KD + wh * 4;
    float4 wreg = *reinterpret_cast<const float4*>(wsrc);

    float s0 = 0.f, s1 = 0.f;             // adj partial sums (rows 2*wid, 2*wid+1)
    ull acc[4][2];
    #pragma unroll
    for (int rp = 0; rp < 4; ++rp) { acc[rp][0] = 0ULL; acc[rp][1] = 0ULL; }

    float* wsm = reinterpret_cast<float*>(smemc + OFF_W);
    const float* xsm = reinterpret_cast<const float*>(smemc + OFF_X);

    for (int i = 0; i < NITER; ++i) {
        const int b = i & 1;
        mbar_wait(b ? mb_full1 : mb_full0, (i >> 1) & 1);
        if (i == 0) mbar_wait(mb_x, 0);

        // store prefetched W chunk i into ws[b]
        {
            float* d = wsm + b * (ED * WSP) + we * WSP + wh * 4;
            d[0] = wreg.x; d[1] = wreg.y; d[2] = wreg.z; d[3] = wreg.w;
        }
        __syncthreads();   // ws[b] visible; stage i-1 buffers fully consumed

        if (i + 1 < NITER) {
            wreg = *reinterpret_cast<const float4*>(wsrc + (i + 1) * KC);
            if (tid == 0) {
                const uint32_t mb = b ? mb_full0 : mb_full1;
                mbar_expect(mb, BR * AC * 4);
                const float* srcA = adj + (size_t)r0 * NN + (size_t)(i + 1) * AC;
                const uint32_t dstA = sb + OFF_ADJ + (1 - b) * ADJ_STAGE;
                #pragma unroll 4
                for (int r = 0; r < BR; ++r)
                    bulk_g2s(dstA + r * (AC * 4), srcA + (size_t)r * NN,
                             AC * 4, mb);
            }
        }

        // ---- adj partial sums from smem stage b (rows 2*wid, 2*wid+1)
        {
            const float4* p = reinterpret_cast<const float4*>(smemc + OFF_ADJ +
                                                              b * ADJ_STAGE);
            float4 u0 = p[(2 * wid) * 64 + lane];
            float4 u1 = p[(2 * wid) * 64 + lane + 32];
            float4 u2 = p[(2 * wid + 1) * 64 + lane];
            float4 u3 = p[(2 * wid + 1) * 64 + lane + 32];
            s0 += (u0.x + u0.y) + (u0.z + u0.w) + (u1.x + u1.y) + (u1.z + u1.w);
            s1 += (u2.x + u2.y) + (u2.z + u2.w) + (u3.x + u3.y) + (u3.z + u3.w);
        }

        // ---- GEMM chunk i: 8 rows x 64 cols per warp, k = 8
        {
            const float* wb = wsm + b * (ED * WSP);
            const float* xrow = xsm + rg * 8 * KD + i * KC;
            const int e0 = eg * 64 + lane;
            #pragma unroll
            for (int h = 0; h < 2; ++h) {
                float a4[8][4];
                #pragma unroll
                for (int r = 0; r < 8; ++r) {
                    const float4 v = *reinterpret_cast<const float4*>(
                        xrow + r * KD + h * 4);
                    a4[r][0] = v.x; a4[r][1] = v.y; a4[r][2] = v.z; a4[r][3] = v.w;
                }
                #pragma unroll
                for (int k2 = 0; k2 < 4; ++k2) {
                    const int kk = h * 4 + k2;
                    const float blo = wb[e0 * WSP + kk];
                    const float bhi = wb[(e0 + 32) * WSP + kk];
                    const ull b2lo = pk2(blo, blo);
                    const ull b2hi = pk2(bhi, bhi);
                    #pragma unroll
                    for (int rp = 0; rp < 4; ++rp) {
                        const ull a2 = pk2(a4[2 * rp][k2], a4[2 * rp + 1][k2]);
                        acc[rp][0] = fma2(a2, b2lo, acc[rp][0]);
                        acc[rp][1] = fma2(a2, b2hi, acc[rp][1]);
                    }
                }
            }
        }
    }

    // ---- epilogue: finish rowsums -> d, then scaled ReLU stores
    #pragma unroll
    for (int o = 16; o; o >>= 1) {
        s0 += __shfl_xor_sync(0xffffffffu, s0, o);
        s1 += __shfl_xor_sync(0xffffffffu, s1, o);
    }
    float* dsm = reinterpret_cast<float*>(smemc + OFF_D);
    if (lane == 0) {
        dsm[2 * wid]     = 1.f / (s0 + 1.f) + 1.f;
        dsm[2 * wid + 1] = 1.f / (s1 + 1.f) + 1.f;
    }
    __syncthreads();

    #pragma unroll
    for (int rp = 0; rp < 4; ++rp) {
        const int ra = 8 * rg + 2 * rp;
        const float d0 = dsm[ra];
        const float d1 = dsm[ra + 1];
        #pragma unroll
        for (int s = 0; s < 2; ++s) {
            float v0, v1;
            upk2(acc[rp][s], v0, v1);
            const int e = eg * 64 + lane + 32 * s;
            out[(size_t)(r0 + ra) * ED + e]     = d0 * fmaxf(v0, 0.f);
            out[(size_t)(r0 + ra + 1) * ED + e] = d1 * fmaxf(v1, 0.f);
        }
    }
}

extern "C" void kernel_launch(void* const* d_in, const int* in_sizes, int n_in,
                              void* d_out, int out_size) {
    (void)in_sizes; (void)n_in; (void)out_size;
    const float* adj = (const float*)d_in[0];
    const float* x   = (const float*)d_in[1];
    const float* W   = (const float*)d_in[2];
    float* out       = (float*)d_out;
    cudaFuncSetAttribute(fused_gcn_tma,
                         cudaFuncAttributeMaxDynamicSharedMemorySize, SMEM_BYTES);
    fused_gcn_tma<<<NN / BR, NT, SMEM_BYTES>>>(adj, x, W, out);
}

// round 3
// speedup vs baseline: 1.6165x; 1.6165x over previous
#include <cuda_runtime.h>
#include <cstdint>
#include <cstddef>

#define NN 16384
#define KD 512
#define ED 256
#define BR 32
#define NSTAGE 6
#define STAGE_BYTES 16384      // 4096 floats = one quarter of a 16384-float row
#define STAGE_F4 1024          // float4 per stage
#define NITER 128              // 2MB adj slab / 16KB
#define KC 4                   // GEMM k per iteration (512/128)
#define NT 256
#define SMEM_BYTES (NSTAGE * STAGE_BYTES)

typedef unsigned long long ull;

__device__ float Wt_g[KD * ED];   // W transposed: Wt[k][e], 512KB

__device__ __forceinline__ ull pk2(float lo, float hi) {
    ull r; asm("mov.b64 %0, {%1, %2};" : "=l"(r) : "f"(lo), "f"(hi)); return r;
}
__device__ __forceinline__ void upk2(ull v, float& lo, float& hi) {
    asm("mov.b64 {%0, %1}, %2;" : "=f"(lo), "=f"(hi) : "l"(v));
}
__device__ __forceinline__ ull fma2(ull a, ull b, ull c) {
    ull d; asm("fma.rn.f32x2 %0, %1, %2, %3;" : "=l"(d) : "l"(a), "l"(b), "l"(c));
    return d;
}
__device__ __forceinline__ ull add2(ull a, ull b) {
    ull d; asm("add.rn.f32x2 %0, %1, %2;" : "=l"(d) : "l"(a), "l"(b));
    return d;
}
__device__ __forceinline__ uint32_t s2u(const void* p) {
    uint32_t a;
    asm("{ .reg .u64 t; cvta.to.shared.u64 t, %1; cvt.u32.u64 %0, t; }"
        : "=r"(a) : "l"(p));
    return a;
}
__device__ __forceinline__ void mbar_init(uint32_t mb, uint32_t cnt) {
    asm volatile("mbarrier.init.shared.b64 [%0], %1;" :: "r"(mb), "r"(cnt) : "memory");
}
__device__ __forceinline__ void mbar_expect(uint32_t mb, uint32_t bytes) {
    asm volatile("mbarrier.arrive.expect_tx.shared.b64 _, [%0], %1;"
                 :: "r"(mb), "r"(bytes) : "memory");
}
__device__ __forceinline__ void mbar_wait(uint32_t mb, uint32_t ph) {
    asm volatile(
        "{\n\t.reg .pred P;\n\t"
        "WL%=:\n\t"
        "mbarrier.try_wait.parity.acquire.cta.shared::cta.b64 P, [%0], %1, 0x989680;\n\t"
        "@P bra WD%=;\n\t"
        "bra WL%=;\n\t"
        "WD%=:\n\t}"
        :: "r"(mb), "r"(ph) : "memory");
}
__device__ __forceinline__ void bulk_g2s(uint32_t dst, const void* src,
                                         uint32_t bytes, uint32_t mb) {
    asm volatile(
        "cp.async.bulk.shared::cta.global.mbarrier::complete_tx::bytes [%0], [%1], %2, [%3];"
        :: "r"(dst), "l"(src), "r"(bytes), "r"(mb) : "memory");
}

// ---------------- W transpose: Wt[k][e] = W[e][k] -------------------------
__global__ void transpose_w(const float* __restrict__ W) {
    __shared__ float t[32][33];
    const int bk = blockIdx.x * 32;   // k-dim tile base (0..511)
    const int be = blockIdx.y * 32;   // e-dim tile base (0..255)
    const int tx = threadIdx.x, ty = threadIdx.y;   // 32 x 8
    #pragma unroll
    for (int j = 0; j < 32; j += 8)
        t[ty + j][tx] = W[(size_t)(be + ty + j) * KD + bk + tx];
    __syncthreads();
    #pragma unroll
    for (int j = 0; j < 32; j += 8)
        Wt_g[(size_t)(bk + ty + j) * ED + be + tx] = t[tx][ty + j];
}

// ---------------- fused streaming rowsum + GEMM ---------------------------
extern __shared__ char smemc[];   // adj ring: NSTAGE * 16KB

__global__ void __launch_bounds__(NT, 2)
fused_gcn3(const float* __restrict__ adj,
           const float* __restrict__ x,
           float* __restrict__ out)
{
    __shared__ float rsum[BR];
    __shared__ ull   mbar[NSTAGE];

    const int tid  = threadIdx.x;
    const int lane = tid & 31;
    const int wid  = tid >> 5;          // 0..7; warp owns out rows 4w..4w+3
    const int r0   = blockIdx.x * BR;

    const uint32_t sb  = s2u(smemc);
    const uint32_t mb0 = s2u(mbar);

    if (tid < BR) rsum[tid] = 0.f;
    if (tid == 0) {
        #pragma unroll
        for (int s = 0; s < NSTAGE; ++s) mbar_init(mb0 + 8 * s, 1);
    }
    __syncthreads();

    const float* adjsrc = adj + (size_t)r0 * NN;   // contiguous 2MB slab
    if (tid == 0) {
        #pragma unroll
        for (int s = 0; s < NSTAGE; ++s) {
            mbar_expect(mb0 + 8 * s, STAGE_BYTES);
            bulk_g2s(sb + s * STAGE_BYTES, adjsrc + (size_t)s * (STAGE_F4 * 4),
                     STAGE_BYTES, mb0 + 8 * s);
        }
    }

    const float* xrow = x + (size_t)(r0 + 4 * wid) * KD;

    ull acc2[4][4];
    #pragma unroll
    for (int r = 0; r < 4; ++r)
        #pragma unroll
        for (int j = 0; j < 4; ++j) acc2[r][j] = 0ULL;

    ull s2 = 0ULL;          // running f32x2 partial of current adj row
    int stg = 0, ph = 0;

    for (int i = 0; i < NITER; ++i) {
        mbar_wait(mb0 + 8 * stg, ph);

        // ---- issue GEMM operand loads first (hide behind rowsum work) ----
        float4 b4[KC][2];
        {
            const float* wk = Wt_g + (size_t)(i * KC) * ED + 4 * lane;
            #pragma unroll
            for (int kk = 0; kk < KC; ++kk) {
                b4[kk][0] = *reinterpret_cast<const float4*>(wk + kk * ED);
                b4[kk][1] = *reinterpret_cast<const float4*>(wk + kk * ED + 128);
            }
        }
        float a_[4][KC];
        #pragma unroll
        for (int r = 0; r < 4; ++r) {
            const float4 v = *reinterpret_cast<const float4*>(
                xrow + (size_t)r * KD + i * KC);
            a_[r][0] = v.x; a_[r][1] = v.y; a_[r][2] = v.z; a_[r][3] = v.w;
        }

        // ---- adj rowsum: thread-contiguous float4 LDS (conflict-free) ----
        {
            const float4* ap = reinterpret_cast<const float4*>(
                smemc + stg * STAGE_BYTES);
            #pragma unroll
            for (int c = 0; c < 4; ++c) {
                const float4 v = ap[tid + 256 * c];
                s2 = add2(s2, pk2(v.x, v.y));
                s2 = add2(s2, pk2(v.z, v.w));
            }
        }

        // ---- GEMM: 4 rows x 256 cols per warp, k = 4 ---------------------
        #pragma unroll
        for (int kk = 0; kk < KC; ++kk) {
            ull b2[4];
            b2[0] = pk2(b4[kk][0].x, b4[kk][0].y);
            b2[1] = pk2(b4[kk][0].z, b4[kk][0].w);
            b2[2] = pk2(b4[kk][1].x, b4[kk][1].y);
            b2[3] = pk2(b4[kk][1].z, b4[kk][1].w);
            #pragma unroll
            for (int r = 0; r < 4; ++r) {
                const ull a2 = pk2(a_[r][kk], a_[r][kk]);
                #pragma unroll
                for (int j = 0; j < 4; ++j)
                    acc2[r][j] = fma2(a2, b2[j], acc2[r][j]);
            }
        }

        // ---- row completes every 4 stages: reduce + atomic ----------------
        if ((i & 3) == 3) {
            float lo, hi; upk2(s2, lo, hi);
            float s = lo + hi;
            #pragma unroll
            for (int o = 16; o; o >>= 1) s += __shfl_xor_sync(0xffffffffu, s, o);
            if (lane == 0) atomicAdd(&rsum[i >> 2], s);
            s2 = 0ULL;
        }

        __syncthreads();    // whole CTA done with stage stg

        if (tid == 0 && i + NSTAGE < NITER) {
            mbar_expect(mb0 + 8 * stg, STAGE_BYTES);
            bulk_g2s(sb + stg * STAGE_BYTES,
                     adjsrc + (size_t)(i + NSTAGE) * (STAGE_F4 * 4),
                     STAGE_BYTES, mb0 + 8 * stg);
        }
        if (++stg == NSTAGE) { stg = 0; ph ^= 1; }
    }

    __syncthreads();        // rsum final

    // ---- epilogue: d = 1/(s+1)+1 ; out = d * relu(acc) -------------------
    #pragma unroll
    for (int r = 0; r < 4; ++r) {
        const float s = rsum[4 * wid + r];
        const float d = 1.f / (s + 1.f) + 1.f;
        float* ob = out + (size_t)(r0 + 4 * wid + r) * ED + 4 * lane;
        #pragma unroll
        for (int h = 0; h < 2; ++h) {
            float v0, v1, v2, v3;
            upk2(acc2[r][2 * h],     v0, v1);
            upk2(acc2[r][2 * h + 1], v2, v3);
            float4 o;
            o.x = d * fmaxf(v0, 0.f);
            o.y = d * fmaxf(v1, 0.f);
            o.z = d * fmaxf(v2, 0.f);
            o.w = d * fmaxf(v3, 0.f);
            *reinterpret_cast<float4*>(ob + 128 * h) = o;
        }
    }
}

extern "C" void kernel_launch(void* const* d_in, const int* in_sizes, int n_in,
                              void* d_out, int out_size) {
    (void)in_sizes; (void)n_in; (void)out_size;
    const float* adj = (const float*)d_in[0];
    const float* x   = (const float*)d_in[1];
    const float* W   = (const float*)d_in[2];
    float* out       = (float*)d_out;

    transpose_w<<<dim3(KD / 32, ED / 32), dim3(32, 8)>>>(W);

    cudaFuncSetAttribute(fused_gcn3,
                         cudaFuncAttributeMaxDynamicSharedMemorySize, SMEM_BYTES);
    fused_gcn3<<<NN / BR, NT, SMEM_BYTES>>>(adj, x, out);
}

// round 4
// speedup vs baseline: 2.1455x; 1.3273x over previous
#include <cuda_runtime.h>
#include <cstdint>
#include <cstddef>

#define NN 16384
#define KD 512
#define ED 256
#define BR 32
#define NT 512
#define NCHUNK 256          // k-chunks of 2

typedef unsigned long long ull;

__device__ float Wt_g[KD * ED];   // W transposed: Wt[k][e]

__device__ __forceinline__ ull pk2(float lo, float hi) {
    ull r; asm("mov.b64 %0, {%1, %2};" : "=l"(r) : "f"(lo), "f"(hi)); return r;
}
__device__ __forceinline__ void upk2(ull v, float& lo, float& hi) {
    asm("mov.b64 {%0, %1}, %2;" : "=f"(lo), "=f"(hi) : "l"(v));
}
__device__ __forceinline__ ull fma2(ull a, ull b, ull c) {
    ull d; asm("fma.rn.f32x2 %0, %1, %2, %3;" : "=l"(d) : "l"(a), "l"(b), "l"(c));
    return d;
}

// ---------------- W transpose: Wt[k][e] = W[e][k] -------------------------
__global__ void transpose_w(const float* __restrict__ W) {
    __shared__ float t[32][33];
    const int bk = blockIdx.x * 32;
    const int be = blockIdx.y * 32;
    const int tx = threadIdx.x, ty = threadIdx.y;   // 32 x 8
    #pragma unroll
    for (int j = 0; j < 32; j += 8)
        t[ty + j][tx] = W[(size_t)(be + ty + j) * KD + bk + tx];
    __syncthreads();
    #pragma unroll
    for (int j = 0; j < 32; j += 8)
        Wt_g[(size_t)(bk + ty + j) * ED + be + tx] = t[tx][ty + j];
}

// ---------------- fused: warp-specialized rowsum stream + GEMM ------------
__global__ void __launch_bounds__(NT, 1)
fused_gcn4(const float* __restrict__ adj,
           const float* __restrict__ x,
           float* __restrict__ out)
{
    __shared__ float dsm[BR];

    const int tid  = threadIdx.x;
    const int wid  = tid >> 5;
    const int lane = tid & 31;
    const int r0   = blockIdx.x * BR;

    if (wid < 8) {
        // ===== STREAM WARPS: rowsums of rows 4*wid .. 4*wid+3 =============
        #pragma unroll 1
        for (int r = 0; r < 4; ++r) {
            const int row = 4 * wid + r;
            const float4* p = reinterpret_cast<const float4*>(
                adj + (size_t)(r0 + row) * NN) + lane;
            float s0 = 0.f, s1 = 0.f, s2 = 0.f, s3 = 0.f;
            #pragma unroll 1
            for (int j = 0; j < 128; j += 8) {
                // 8 independent LDG.128 in flight
                float4 v0 = __ldcs(p + (j + 0) * 32);
                float4 v1 = __ldcs(p + (j + 1) * 32);
                float4 v2 = __ldcs(p + (j + 2) * 32);
                float4 v3 = __ldcs(p + (j + 3) * 32);
                float4 v4 = __ldcs(p + (j + 4) * 32);
                float4 v5 = __ldcs(p + (j + 5) * 32);
                float4 v6 = __ldcs(p + (j + 6) * 32);
                float4 v7 = __ldcs(p + (j + 7) * 32);
                s0 += (v0.x + v0.y) + (v0.z + v0.w);
                s1 += (v1.x + v1.y) + (v1.z + v1.w);
                s2 += (v2.x + v2.y) + (v2.z + v2.w);
                s3 += (v3.x + v3.y) + (v3.z + v3.w);
                s0 += (v4.x + v4.y) + (v4.z + v4.w);
                s1 += (v5.x + v5.y) + (v5.z + v5.w);
                s2 += (v6.x + v6.y) + (v6.z + v6.w);
                s3 += (v7.x + v7.y) + (v7.z + v7.w);
            }
            float s = (s0 + s1) + (s2 + s3);
            #pragma unroll
            for (int o = 16; o; o >>= 1) s += __shfl_xor_sync(0xffffffffu, s, o);
            if (lane == 0) dsm[row] = 1.f / (s + 1.f) + 1.f;
        }
        __syncthreads();
    } else {
        // ===== GEMM WARPS: rows 4*g..4*g+3, all 256 cols ==================
        const int g = wid - 8;
        const float* xb = x + (size_t)(r0 + 4 * g) * KD;
        const float* wb = Wt_g + 4 * lane;

        ull acc[4][4];
        #pragma unroll
        for (int r = 0; r < 4; ++r)
            #pragma unroll
            for (int j = 0; j < 4; ++j) acc[r][j] = 0ULL;

        // software pipeline: chunk = 2 k-steps
        float4 bc0, bc1, bc2, bc3;       // b: k0 cols[0:4),k0 cols[128:132),k1...
        float2 ac[4];                    // a: per row, 2 k-values
        bc0 = *reinterpret_cast<const float4*>(wb);
        bc1 = *reinterpret_cast<const float4*>(wb + 128);
        bc2 = *reinterpret_cast<const float4*>(wb + ED);
        bc3 = *reinterpret_cast<const float4*>(wb + ED + 128);
        #pragma unroll
        for (int r = 0; r < 4; ++r)
            ac[r] = *reinterpret_cast<const float2*>(xb + (size_t)r * KD);

        #pragma unroll 2
        for (int c = 0; c < NCHUNK; ++c) {
            float4 bn0, bn1, bn2, bn3;
            float2 an[4];
            if (c + 1 < NCHUNK) {
                const float* wn = wb + (size_t)(2 * (c + 1)) * ED;
                bn0 = *reinterpret_cast<const float4*>(wn);
                bn1 = *reinterpret_cast<const float4*>(wn + 128);
                bn2 = *reinterpret_cast<const float4*>(wn + ED);
                bn3 = *reinterpret_cast<const float4*>(wn + ED + 128);
                #pragma unroll
                for (int r = 0; r < 4; ++r)
                    an[r] = *reinterpret_cast<const float2*>(
                        xb + (size_t)r * KD + 2 * (c + 1));
            }
            // k = 0
            {
                ull b2[4];
                b2[0] = pk2(bc0.x, bc0.y); b2[1] = pk2(bc0.z, bc0.w);
                b2[2] = pk2(bc1.x, bc1.y); b2[3] = pk2(bc1.z, bc1.w);
                #pragma unroll
                for (int r = 0; r < 4; ++r) {
                    const ull a2 = pk2(ac[r].x, ac[r].x);
                    #pragma unroll
                    for (int j = 0; j < 4; ++j) acc[r][j] = fma2(a2, b2[j], acc[r][j]);
                }
            }
            // k = 1
            {
                ull b2[4];
                b2[0] = pk2(bc2.x, bc2.y); b2[1] = pk2(bc2.z, bc2.w);
                b2[2] = pk2(bc3.x, bc3.y); b2[3] = pk2(bc3.z, bc3.w);
                #pragma unroll
                for (int r = 0; r < 4; ++r) {
                    const ull a2 = pk2(ac[r].y, ac[r].y);
                    #pragma unroll
                    for (int j = 0; j < 4; ++j) acc[r][j] = fma2(a2, b2[j], acc[r][j]);
                }
            }
            bc0 = bn0; bc1 = bn1; bc2 = bn2; bc3 = bn3;
            #pragma unroll
            for (int r = 0; r < 4; ++r) ac[r] = an[r];
        }

        __syncthreads();   // dsm ready

        #pragma unroll
        for (int r = 0; r < 4; ++r) {
            const float d = dsm[4 * g + r];
            float* ob = out + (size_t)(r0 + 4 * g + r) * ED + 4 * lane;
            #pragma unroll
            for (int h = 0; h < 2; ++h) {
                float v0, v1, v2, v3;
                upk2(acc[r][2 * h],     v0, v1);
                upk2(acc[r][2 * h + 1], v2, v3);
                float4 o;
                o.x = d * fmaxf(v0, 0.f);
                o.y = d * fmaxf(v1, 0.f);
                o.z = d * fmaxf(v2, 0.f);
                o.w = d * fmaxf(v3, 0.f);
                *reinterpret_cast<float4*>(ob + 128 * h) = o;
            }
        }
    }
}

extern "C" void kernel_launch(void* const* d_in, const int* in_sizes, int n_in,
                              void* d_out, int out_size) {
    (void)in_sizes; (void)n_in; (void)out_size;
    const float* adj = (const float*)d_in[0];
    const float* x   = (const float*)d_in[1];
    const float* W   = (const float*)d_in[2];
    float* out       = (float*)d_out;

    transpose_w<<<dim3(KD / 32, ED / 32), dim3(32, 8)>>>(W);
    fused_gcn4<<<NN / BR, NT>>>(adj, x, out);
}

// round 5
// speedup vs baseline: 2.1459x; 1.0002x over previous
#include <cuda_runtime.h>
#include <cstdint>
#include <cstddef>

#define NN 16384
#define KD 512
#define ED 256
#define BR 32
#define NT 512
#define KCH 32                    // k per chunk
#define NCH (KD / KCH)            // 16 chunks
#define CHUNK_BYTES (KCH * ED * 4)      // 32 KB
#define SMEM_BYTES (2 * CHUNK_BYTES)    // 64 KB ring

typedef unsigned long long ull;

__device__ float Wt_g[KD * ED];   // W transposed: Wt[k][e]

__device__ __forceinline__ ull pk2(float lo, float hi) {
    ull r; asm("mov.b64 %0, {%1, %2};" : "=l"(r) : "f"(lo), "f"(hi)); return r;
}
__device__ __forceinline__ void upk2(ull v, float& lo, float& hi) {
    asm("mov.b64 {%0, %1}, %2;" : "=f"(lo), "=f"(hi) : "l"(v));
}
__device__ __forceinline__ ull fma2(ull a, ull b, ull c) {
    ull d; asm("fma.rn.f32x2 %0, %1, %2, %3;" : "=l"(d) : "l"(a), "l"(b), "l"(c));
    return d;
}
__device__ __forceinline__ uint32_t s2u(const void* p) {
    uint32_t a;
    asm("{ .reg .u64 t; cvta.to.shared.u64 t, %1; cvt.u32.u64 %0, t; }"
        : "=r"(a) : "l"(p));
    return a;
}
__device__ __forceinline__ void mbar_init(uint32_t mb, uint32_t cnt) {
    asm volatile("mbarrier.init.shared.b64 [%0], %1;" :: "r"(mb), "r"(cnt) : "memory");
}
__device__ __forceinline__ void mbar_expect(uint32_t mb, uint32_t bytes) {
    asm volatile("mbarrier.arrive.expect_tx.shared.b64 _, [%0], %1;"
                 :: "r"(mb), "r"(bytes) : "memory");
}
__device__ __forceinline__ void mbar_wait(uint32_t mb, uint32_t ph) {
    asm volatile(
        "{\n\t.reg .pred P;\n\t"
        "WL%=:\n\t"
        "mbarrier.try_wait.parity.acquire.cta.shared::cta.b64 P, [%0], %1, 0x989680;\n\t"
        "@P bra WD%=;\n\t"
        "bra WL%=;\n\t"
        "WD%=:\n\t}"
        :: "r"(mb), "r"(ph) : "memory");
}
__device__ __forceinline__ void bulk_g2s(uint32_t dst, const void* src,
                                         uint32_t bytes, uint32_t mb) {
    asm volatile(
        "cp.async.bulk.shared::cta.global.mbarrier::complete_tx::bytes [%0], [%1], %2, [%3];"
        :: "r"(dst), "l"(src), "r"(bytes), "r"(mb) : "memory");
}
__device__ __forceinline__ void bar_gemm() {   // named barrier: GEMM warps only
    asm volatile("bar.sync 1, 256;" ::: "memory");
}

// ---------------- W transpose: Wt[k][e] = W[e][k] -------------------------
__global__ void transpose_w(const float* __restrict__ W) {
    __shared__ float t[32][33];
    const int bk = blockIdx.x * 32;
    const int be = blockIdx.y * 32;
    const int tx = threadIdx.x, ty = threadIdx.y;   // 32 x 8
    #pragma unroll
    for (int j = 0; j < 32; j += 8)
        t[ty + j][tx] = W[(size_t)(be + ty + j) * KD + bk + tx];
    __syncthreads();
    #pragma unroll
    for (int j = 0; j < 32; j += 8)
        Wt_g[(size_t)(bk + ty + j) * ED + be + tx] = t[tx][ty + j];
}

// ---------------- fused: stream warps + smem-staged GEMM warps ------------
extern __shared__ float ws[];     // 2 x (32 x 256) floats

__global__ void __launch_bounds__(NT, 1)
fused_gcn5(const float* __restrict__ adj,
           const float* __restrict__ x,
           float* __restrict__ out)
{
    __shared__ float dsm[BR];
    __shared__ ull   mbar[2];

    const int tid  = threadIdx.x;
    const int wid  = tid >> 5;
    const int lane = tid & 31;
    const int r0   = blockIdx.x * BR;

    const uint32_t wsb = s2u(ws);
    const uint32_t mb0 = s2u(mbar);

    if (tid == 256) {
        mbar_init(mb0, 1);
        mbar_init(mb0 + 8, 1);
    }
    __syncthreads();

    if (wid < 8) {
        // ===== STREAM WARPS: rowsums of rows 4*wid .. 4*wid+3 =============
        #pragma unroll 1
        for (int r = 0; r < 4; ++r) {
            const int row = 4 * wid + r;
            const float4* p = reinterpret_cast<const float4*>(
                adj + (size_t)(r0 + row) * NN) + lane;
            float s0 = 0.f, s1 = 0.f, s2 = 0.f, s3 = 0.f;
            #pragma unroll 1
            for (int j = 0; j < 128; j += 8) {
                float4 v0 = __ldcs(p + (j + 0) * 32);
                float4 v1 = __ldcs(p + (j + 1) * 32);
                float4 v2 = __ldcs(p + (j + 2) * 32);
                float4 v3 = __ldcs(p + (j + 3) * 32);
                float4 v4 = __ldcs(p + (j + 4) * 32);
                float4 v5 = __ldcs(p + (j + 5) * 32);
                float4 v6 = __ldcs(p + (j + 6) * 32);
                float4 v7 = __ldcs(p + (j + 7) * 32);
                s0 += (v0.x + v0.y) + (v0.z + v0.w);
                s1 += (v1.x + v1.y) + (v1.z + v1.w);
                s2 += (v2.x + v2.y) + (v2.z + v2.w);
                s3 += (v3.x + v3.y) + (v3.z + v3.w);
                s0 += (v4.x + v4.y) + (v4.z + v4.w);
                s1 += (v5.x + v5.y) + (v5.z + v5.w);
                s2 += (v6.x + v6.y) + (v6.z + v6.w);
                s3 += (v7.x + v7.y) + (v7.z + v7.w);
            }
            float s = (s0 + s1) + (s2 + s3);
            #pragma unroll
            for (int o = 16; o; o >>= 1) s += __shfl_xor_sync(0xffffffffu, s, o);
            if (lane == 0) dsm[row] = 1.f / (s + 1.f) + 1.f;
        }
        __syncthreads();
    } else {
        // ===== GEMM WARPS (wid 8..15): rows 4*g..4*g+3, 256 cols ==========
        const int g = wid - 8;
        const float* xb = x + (size_t)(r0 + 4 * g) * KD;

        // prologue: elect issues first two chunk loads
        if (tid == 256) {
            mbar_expect(mb0, CHUNK_BYTES);
            bulk_g2s(wsb, Wt_g, CHUNK_BYTES, mb0);
            mbar_expect(mb0 + 8, CHUNK_BYTES);
            bulk_g2s(wsb + CHUNK_BYTES, Wt_g + KCH * ED, CHUNK_BYTES, mb0 + 8);
        }

        ull acc[4][4];
        #pragma unroll
        for (int r = 0; r < 4; ++r)
            #pragma unroll
            for (int j = 0; j < 4; ++j) acc[r][j] = 0ULL;

        #pragma unroll 1
        for (int c = 0; c < NCH; ++c) {
            const int b = c & 1;
            mbar_wait(mb0 + 8 * b, (c >> 1) & 1);

            const float* wsm = ws + b * (KCH * ED) + 4 * lane;
            #pragma unroll
            for (int q = 0; q < KCH / 4; ++q) {
                float a4[4][4];
                #pragma unroll
                for (int r = 0; r < 4; ++r) {     // warp-uniform broadcast
                    const float4 v = *reinterpret_cast<const float4*>(
                        xb + (size_t)r * KD + c * KCH + q * 4);
                    a4[r][0] = v.x; a4[r][1] = v.y; a4[r][2] = v.z; a4[r][3] = v.w;
                }
                #pragma unroll
                for (int t = 0; t < 4; ++t) {
                    const int kk = q * 4 + t;
                    const float4 blo = *reinterpret_cast<const float4*>(
                        wsm + kk * ED);
                    const float4 bhi = *reinterpret_cast<const float4*>(
                        wsm + kk * ED + 128);
                    ull b2[4];
                    b2[0] = pk2(blo.x, blo.y); b2[1] = pk2(blo.z, blo.w);
                    b2[2] = pk2(bhi.x, bhi.y); b2[3] = pk2(bhi.z, bhi.w);
                    #pragma unroll
                    for (int r = 0; r < 4; ++r) {
                        const ull a2 = pk2(a4[r][t], a4[r][t]);
                        #pragma unroll
                        for (int j = 0; j < 4; ++j)
                            acc[r][j] = fma2(a2, b2[j], acc[r][j]);
                    }
                }
            }

            bar_gemm();   // all GEMM warps done with buffer b
            if (tid == 256 && c + 2 < NCH) {
                mbar_expect(mb0 + 8 * b, CHUNK_BYTES);
                bulk_g2s(wsb + b * CHUNK_BYTES,
                         Wt_g + (size_t)(c + 2) * KCH * ED,
                         CHUNK_BYTES, mb0 + 8 * b);
            }
        }

        __syncthreads();   // dsm ready from stream warps

        #pragma unroll
        for (int r = 0; r < 4; ++r) {
            const float d = dsm[4 * g + r];
            float* ob = out + (size_t)(r0 + 4 * g + r) * ED + 4 * lane;
            #pragma unroll
            for (int h = 0; h < 2; ++h) {
                float v0, v1, v2, v3;
                upk2(acc[r][2 * h],     v0, v1);
                upk2(acc[r][2 * h + 1], v2, v3);
                float4 o;
                o.x = d * fmaxf(v0, 0.f);
                o.y = d * fmaxf(v1, 0.f);
                o.z = d * fmaxf(v2, 0.f);
                o.w = d * fmaxf(v3, 0.f);
                *reinterpret_cast<float4*>(ob + 128 * h) = o;
            }
        }
    }
}

extern "C" void kernel_launch(void* const* d_in, const int* in_sizes, int n_in,
                              void* d_out, int out_size) {
    (void)in_sizes; (void)n_in; (void)out_size;
    const float* adj = (const float*)d_in[0];
    const float* x   = (const float*)d_in[1];
    const float* W   = (const float*)d_in[2];
    float* out       = (float*)d_out;

    transpose_w<<<dim3(KD / 32, ED / 32), dim3(32, 8)>>>(W);

    cudaFuncSetAttribute(fused_gcn5,
                         cudaFuncAttributeMaxDynamicSharedMemorySize, SMEM_BYTES);
    fused_gcn5<<<NN / BR, NT, SMEM_BYTES>>>(adj, x, out);
}

// round 6
// speedup vs baseline: 2.4783x; 1.1549x over previous
#include <cuda_runtime.h>
#include <cstdint>
#include <cstddef>

#define NN 16384
#define KD 512
#define ED 256
#define BR 32
#define NT 512
#define KCH 32                    // k per chunk
#define NCH (KD / KCH)            // 16 chunks
#define CHUNK_BYTES (KCH * ED * 4)      // 32 KB
#define SMEM_BYTES (2 * CHUNK_BYTES)    // 64 KB ring

typedef unsigned long long ull;

__device__ float Wt_g[KD * ED];   // W transposed: Wt[k][e]

__device__ __forceinline__ ull pk2(float lo, float hi) {
    ull r; asm("mov.b64 %0, {%1, %2};" : "=l"(r) : "f"(lo), "f"(hi)); return r;
}
__device__ __forceinline__ void upk2(ull v, float& lo, float& hi) {
    asm("mov.b64 {%0, %1}, %2;" : "=f"(lo), "=f"(hi) : "l"(v));
}
__device__ __forceinline__ ull fma2(ull a, ull b, ull c) {
    ull d; asm("fma.rn.f32x2 %0, %1, %2, %3;" : "=l"(d) : "l"(a), "l"(b), "l"(c));
    return d;
}
__device__ __forceinline__ uint32_t s2u(const void* p) {
    uint32_t a;
    asm("{ .reg .u64 t; cvta.to.shared.u64 t, %1; cvt.u32.u64 %0, t; }"
        : "=r"(a) : "l"(p));
    return a;
}
__device__ __forceinline__ void mbar_init(uint32_t mb, uint32_t cnt) {
    asm volatile("mbarrier.init.shared.b64 [%0], %1;" :: "r"(mb), "r"(cnt) : "memory");
}
__device__ __forceinline__ void mbar_expect(uint32_t mb, uint32_t bytes) {
    asm volatile("mbarrier.arrive.expect_tx.shared.b64 _, [%0], %1;"
                 :: "r"(mb), "r"(bytes) : "memory");
}
__device__ __forceinline__ void mbar_wait(uint32_t mb, uint32_t ph) {
    asm volatile(
        "{\n\t.reg .pred P;\n\t"
        "WL%=:\n\t"
        "mbarrier.try_wait.parity.acquire.cta.shared::cta.b64 P, [%0], %1, 0x989680;\n\t"
        "@P bra WD%=;\n\t"
        "bra WL%=;\n\t"
        "WD%=:\n\t}"
        :: "r"(mb), "r"(ph) : "memory");
}
__device__ __forceinline__ void bulk_g2s(uint32_t dst, const void* src,
                                         uint32_t bytes, uint32_t mb) {
    asm volatile(
        "cp.async.bulk.shared::cta.global.mbarrier::complete_tx::bytes [%0], [%1], %2, [%3];"
        :: "r"(dst), "l"(src), "r"(bytes), "r"(mb) : "memory");
}
__device__ __forceinline__ void bar_gemm() {   // named barrier: GEMM warps only
    asm volatile("bar.sync 1, 256;" ::: "memory");
}

// ---------------- W transpose: Wt[k][e] = W[e][k] -------------------------
__global__ void transpose_w(const float* __restrict__ W) {
    __shared__ float t[32][33];
    const int bk = blockIdx.x * 32;
    const int be = blockIdx.y * 32;
    const int tx = threadIdx.x, ty = threadIdx.y;   // 32 x 8
    #pragma unroll
    for (int j = 0; j < 32; j += 8)
        t[ty + j][tx] = W[(size_t)(be + ty + j) * KD + bk + tx];
    __syncthreads();
    #pragma unroll
    for (int j = 0; j < 32; j += 8)
        Wt_g[(size_t)(bk + ty + j) * ED + be + tx] = t[tx][ty + j];
}

// ---------------- fused: deep-MLP stream warps + smem-staged GEMM ---------
extern __shared__ float ws[];     // 2 x (32 x 256) floats

__global__ void __launch_bounds__(NT, 1)
fused_gcn6(const float* __restrict__ adj,
           const float* __restrict__ x,
           float* __restrict__ out)
{
    __shared__ float dsm[BR];
    __shared__ ull   mbar[2];

    const int tid  = threadIdx.x;
    const int wid  = tid >> 5;
    const int lane = tid & 31;
    const int r0   = blockIdx.x * BR;

    const uint32_t wsb = s2u(ws);
    const uint32_t mb0 = s2u(mbar);

    if (tid == 256) {
        mbar_init(mb0, 1);
        mbar_init(mb0 + 8, 1);
    }
    __syncthreads();

    if (wid < 8) {
        // ===== STREAM WARPS: rowsums, 16 LDG.128 in flight per thread =====
        #pragma unroll 1
        for (int r = 0; r < 4; ++r) {
            const int row = 4 * wid + r;
            const float4* p = reinterpret_cast<const float4*>(
                adj + (size_t)(r0 + row) * NN) + lane;
            float s0 = 0.f, s1 = 0.f, s2 = 0.f, s3 = 0.f;
            #pragma unroll 1
            for (int j = 0; j < 128; j += 16) {
                float4 v[16];
                #pragma unroll
                for (int t = 0; t < 16; ++t)
                    v[t] = __ldcs(p + (j + t) * 32);
                #pragma unroll
                for (int t = 0; t < 16; t += 4) {
                    s0 += (v[t + 0].x + v[t + 0].y) + (v[t + 0].z + v[t + 0].w);
                    s1 += (v[t + 1].x + v[t + 1].y) + (v[t + 1].z + v[t + 1].w);
                    s2 += (v[t + 2].x + v[t + 2].y) + (v[t + 2].z + v[t + 2].w);
                    s3 += (v[t + 3].x + v[t + 3].y) + (v[t + 3].z + v[t + 3].w);
                }
            }
            float s = (s0 + s1) + (s2 + s3);
            #pragma unroll
            for (int o = 16; o; o >>= 1) s += __shfl_xor_sync(0xffffffffu, s, o);
            if (lane == 0) dsm[row] = 1.f / (s + 1.f) + 1.f;
        }
        __syncthreads();
    } else {
        // ===== GEMM WARPS (wid 8..15): rows 4*g..4*g+3, 256 cols ==========
        const int g = wid - 8;
        const float* xb = x + (size_t)(r0 + 4 * g) * KD;

        if (tid == 256) {
            mbar_expect(mb0, CHUNK_BYTES);
            bulk_g2s(wsb, Wt_g, CHUNK_BYTES, mb0);
            mbar_expect(mb0 + 8, CHUNK_BYTES);
            bulk_g2s(wsb + CHUNK_BYTES, Wt_g + KCH * ED, CHUNK_BYTES, mb0 + 8);
        }

        ull acc[4][4];
        #pragma unroll
        for (int r = 0; r < 4; ++r)
            #pragma unroll
            for (int j = 0; j < 4; ++j) acc[r][j] = 0ULL;

        #pragma unroll 1
        for (int c = 0; c < NCH; ++c) {
            const int b = c & 1;
            mbar_wait(mb0 + 8 * b, (c >> 1) & 1);

            const float* wsm = ws + b * (KCH * ED) + 4 * lane;
            #pragma unroll
            for (int q = 0; q < KCH / 4; ++q) {
                float a4[4][4];
                #pragma unroll
                for (int r = 0; r < 4; ++r) {     // warp-uniform broadcast
                    const float4 v = *reinterpret_cast<const float4*>(
                        xb + (size_t)r * KD + c * KCH + q * 4);
                    a4[r][0] = v.x; a4[r][1] = v.y; a4[r][2] = v.z; a4[r][3] = v.w;
                }
                #pragma unroll
                for (int t = 0; t < 4; ++t) {
                    const int kk = q * 4 + t;
                    const float4 blo = *reinterpret_cast<const float4*>(
                        wsm + kk * ED);
                    const float4 bhi = *reinterpret_cast<const float4*>(
                        wsm + kk * ED + 128);
                    ull b2[4];
                    b2[0] = pk2(blo.x, blo.y); b2[1] = pk2(blo.z, blo.w);
                    b2[2] = pk2(bhi.x, bhi.y); b2[3] = pk2(bhi.z, bhi.w);
                    #pragma unroll
                    for (int r = 0; r < 4; ++r) {
                        const ull a2 = pk2(a4[r][t], a4[r][t]);
                        #pragma unroll
                        for (int j = 0; j < 4; ++j)
                            acc[r][j] = fma2(a2, b2[j], acc[r][j]);
                    }
                }
            }

            bar_gemm();   // all GEMM warps done with buffer b
            if (tid == 256 && c + 2 < NCH) {
                mbar_expect(mb0 + 8 * b, CHUNK_BYTES);
                bulk_g2s(wsb + b * CHUNK_BYTES,
                         Wt_g + (size_t)(c + 2) * KCH * ED,
                         CHUNK_BYTES, mb0 + 8 * b);
            }
        }

        __syncthreads();   // dsm ready from stream warps

        #pragma unroll
        for (int r = 0; r < 4; ++r) {
            const float d = dsm[4 * g + r];
            float* ob = out + (size_t)(r0 + 4 * g + r) * ED + 4 * lane;
            #pragma unroll
            for (int h = 0; h < 2; ++h) {
                float v0, v1, v2, v3;
                upk2(acc[r][2 * h],     v0, v1);
                upk2(acc[r][2 * h + 1], v2, v3);
                float4 o;
                o.x = d * fmaxf(v0, 0.f);
                o.y = d * fmaxf(v1, 0.f);
                o.z = d * fmaxf(v2, 0.f);
                o.w = d * fmaxf(v3, 0.f);
                *reinterpret_cast<float4*>(ob + 128 * h) = o;
            }
        }
    }
}

extern "C" void kernel_launch(void* const* d_in, const int* in_sizes, int n_in,
                              void* d_out, int out_size) {
    (void)in_sizes; (void)n_in; (void)out_size;
    const float* adj = (const float*)d_in[0];
    const float* x   = (const float*)d_in[1];
    const float* W   = (const float*)d_in[2];
    float* out       = (float*)d_out;

    transpose_w<<<dim3(KD / 32, ED / 32), dim3(32, 8)>>>(W);

    cudaFuncSetAttribute(fused_gcn6,
                         cudaFuncAttributeMaxDynamicSharedMemorySize, SMEM_BYTES);
    fused_gcn6<<<NN / BR, NT, SMEM_BYTES>>>(adj, x, out);
}

// round 7
// speedup vs baseline: 2.5292x; 1.0205x over previous
#include <cuda_runtime.h>
#include <cstdint>
#include <cstddef>

#define NN 16384
#define KD 512
#define ED 256
#define BR 16                     // rows per CTA
#define NT 256                    // 4 stream warps + 4 GEMM warps
#define KCH 32                    // k per chunk
#define NCH (KD / KCH)            // 16 chunks
#define CHUNK_BYTES (KCH * ED * 4)      // 32 KB
#define SMEM_BYTES (2 * CHUNK_BYTES)    // 64 KB ring

typedef unsigned long long ull;

__device__ float Wt_g[KD * ED];   // W transposed: Wt[k][e]

__device__ __forceinline__ ull pk2(float lo, float hi) {
    ull r; asm("mov.b64 %0, {%1, %2};" : "=l"(r) : "f"(lo), "f"(hi)); return r;
}
__device__ __forceinline__ void upk2(ull v, float& lo, float& hi) {
    asm("mov.b64 {%0, %1}, %2;" : "=f"(lo), "=f"(hi) : "l"(v));
}
__device__ __forceinline__ ull fma2(ull a, ull b, ull c) {
    ull d; asm("fma.rn.f32x2 %0, %1, %2, %3;" : "=l"(d) : "l"(a), "l"(b), "l"(c));
    return d;
}
__device__ __forceinline__ ull add2(ull a, ull b) {
    ull d; asm("add.rn.f32x2 %0, %1, %2;" : "=l"(d) : "l"(a), "l"(b));
    return d;
}
__device__ __forceinline__ uint32_t s2u(const void* p) {
    uint32_t a;
    asm("{ .reg .u64 t; cvta.to.shared.u64 t, %1; cvt.u32.u64 %0, t; }"
        : "=r"(a) : "l"(p));
    return a;
}
__device__ __forceinline__ void mbar_init(uint32_t mb, uint32_t cnt) {
    asm volatile("mbarrier.init.shared.b64 [%0], %1;" :: "r"(mb), "r"(cnt) : "memory");
}
__device__ __forceinline__ void mbar_expect(uint32_t mb, uint32_t bytes) {
    asm volatile("mbarrier.arrive.expect_tx.shared.b64 _, [%0], %1;"
                 :: "r"(mb), "r"(bytes) : "memory");
}
__device__ __forceinline__ void mbar_wait(uint32_t mb, uint32_t ph) {
    asm volatile(
        "{\n\t.reg .pred P;\n\t"
        "WL%=:\n\t"
        "mbarrier.try_wait.parity.acquire.cta.shared::cta.b64 P, [%0], %1, 0x989680;\n\t"
        "@P bra WD%=;\n\t"
        "bra WL%=;\n\t"
        "WD%=:\n\t}"
        :: "r"(mb), "r"(ph) : "memory");
}
__device__ __forceinline__ void bulk_g2s(uint32_t dst, const void* src,
                                         uint32_t bytes, uint32_t mb) {
    asm volatile(
        "cp.async.bulk.shared::cta.global.mbarrier::complete_tx::bytes [%0], [%1], %2, [%3];"
        :: "r"(dst), "l"(src), "r"(bytes), "r"(mb) : "memory");
}
__device__ __forceinline__ void bar_gemm() {   // named barrier: GEMM warps only
    asm volatile("bar.sync 1, 128;" ::: "memory");
}

// ---------------- W transpose: Wt[k][e] = W[e][k] -------------------------
__global__ void transpose_w(const float* __restrict__ W) {
    __shared__ float t[32][33];
    const int bk = blockIdx.x * 32;
    const int be = blockIdx.y * 32;
    const int tx = threadIdx.x, ty = threadIdx.y;   // 32 x 8
    #pragma unroll
    for (int j = 0; j < 32; j += 8)
        t[ty + j][tx] = W[(size_t)(be + ty + j) * KD + bk + tx];
    __syncthreads();
    #pragma unroll
    for (int j = 0; j < 32; j += 8)
        Wt_g[(size_t)(bk + ty + j) * ED + be + tx] = t[tx][ty + j];
}

// ---------------- fused: deep-MLP stream warps + smem-staged GEMM ---------
extern __shared__ float ws[];     // 2 x (32 x 256) floats

__global__ void __launch_bounds__(NT, 2)
fused_gcn7(const float* __restrict__ adj,
           const float* __restrict__ x,
           float* __restrict__ out)
{
    __shared__ float dsm[BR];
    __shared__ ull   mbar[2];

    const int tid  = threadIdx.x;
    const int wid  = tid >> 5;
    const int lane = tid & 31;
    const int r0   = blockIdx.x * BR;

    const uint32_t wsb = s2u(ws);
    const uint32_t mb0 = s2u(mbar);

    if (tid == 128) {
        mbar_init(mb0, 1);
        mbar_init(mb0 + 8, 1);
    }
    __syncthreads();

    if (wid < 4) {
        // ===== STREAM WARPS: rowsums, 16 LDG.128 in flight per thread =====
        #pragma unroll 1
        for (int r = 0; r < 4; ++r) {
            const int row = 4 * wid + r;
            const float4* p = reinterpret_cast<const float4*>(
                adj + (size_t)(r0 + row) * NN) + lane;
            ull sa = 0ULL, sb = 0ULL, sc = 0ULL, sd = 0ULL;  // f32x2 chains
            #pragma unroll 1
            for (int j = 0; j < 128; j += 16) {
                float4 v[16];
                #pragma unroll
                for (int t = 0; t < 16; ++t)
                    v[t] = __ldcs(p + (j + t) * 32);
                #pragma unroll
                for (int t = 0; t < 16; t += 4) {
                    sa = add2(sa, pk2(v[t + 0].x, v[t + 0].y));
                    sb = add2(sb, pk2(v[t + 0].z, v[t + 0].w));
                    sc = add2(sc, pk2(v[t + 1].x, v[t + 1].y));
                    sd = add2(sd, pk2(v[t + 1].z, v[t + 1].w));
                    sa = add2(sa, pk2(v[t + 2].x, v[t + 2].y));
                    sb = add2(sb, pk2(v[t + 2].z, v[t + 2].w));
                    sc = add2(sc, pk2(v[t + 3].x, v[t + 3].y));
                    sd = add2(sd, pk2(v[t + 3].z, v[t + 3].w));
                }
            }
            sa = add2(sa, sb); sc = add2(sc, sd); sa = add2(sa, sc);
            float lo, hi; upk2(sa, lo, hi);
            float s = lo + hi;
            #pragma unroll
            for (int o = 16; o; o >>= 1) s += __shfl_xor_sync(0xffffffffu, s, o);
            if (lane == 0) dsm[row] = 1.f / (s + 1.f) + 1.f;
        }
        __syncthreads();
    } else {
        // ===== GEMM WARPS (wid 4..7): rows 4*g..4*g+3, 256 cols ===========
        const int g = wid - 4;
        const float* xb = x + (size_t)(r0 + 4 * g) * KD;

        if (tid == 128) {
            mbar_expect(mb0, CHUNK_BYTES);
            bulk_g2s(wsb, Wt_g, CHUNK_BYTES, mb0);
            mbar_expect(mb0 + 8, CHUNK_BYTES);
            bulk_g2s(wsb + CHUNK_BYTES, Wt_g + KCH * ED, CHUNK_BYTES, mb0 + 8);
        }

        ull acc[4][4];
        #pragma unroll
        for (int r = 0; r < 4; ++r)
            #pragma unroll
            for (int j = 0; j < 4; ++j) acc[r][j] = 0ULL;

        #pragma unroll 1
        for (int c = 0; c < NCH; ++c) {
            const int b = c & 1;
            mbar_wait(mb0 + 8 * b, (c >> 1) & 1);

            const float* wsm = ws + b * (KCH * ED) + 4 * lane;
            #pragma unroll
            for (int q = 0; q < KCH / 4; ++q) {
                float a4[4][4];
                #pragma unroll
                for (int r = 0; r < 4; ++r) {     // warp-uniform broadcast
                    const float4 v = *reinterpret_cast<const float4*>(
                        xb + (size_t)r * KD + c * KCH + q * 4);
                    a4[r][0] = v.x; a4[r][1] = v.y; a4[r][2] = v.z; a4[r][3] = v.w;
                }
                #pragma unroll
                for (int t = 0; t < 4; ++t) {
                    const int kk = q * 4 + t;
                    const float4 blo = *reinterpret_cast<const float4*>(
                        wsm + kk * ED);
                    const float4 bhi = *reinterpret_cast<const float4*>(
                        wsm + kk * ED + 128);
                    ull b2[4];
                    b2[0] = pk2(blo.x, blo.y); b2[1] = pk2(blo.z, blo.w);
                    b2[2] = pk2(bhi.x, bhi.y); b2[3] = pk2(bhi.z, bhi.w);
                    #pragma unroll
                    for (int r = 0; r < 4; ++r) {
                        const ull a2 = pk2(a4[r][t], a4[r][t]);
                        #pragma unroll
                        for (int j = 0; j < 4; ++j)
                            acc[r][j] = fma2(a2, b2[j], acc[r][j]);
                    }
                }
            }

            bar_gemm();   // all GEMM warps done with buffer b
            if (tid == 128 && c + 2 < NCH) {
                mbar_expect(mb0 + 8 * b, CHUNK_BYTES);
                bulk_g2s(wsb + b * CHUNK_BYTES,
                         Wt_g + (size_t)(c + 2) * KCH * ED,
                         CHUNK_BYTES, mb0 + 8 * b);
            }
        }

        __syncthreads();   // dsm ready from stream warps

        #pragma unroll
        for (int r = 0; r < 4; ++r) {
            const float d = dsm[4 * g + r];
            float* ob = out + (size_t)(r0 + 4 * g + r) * ED + 4 * lane;
            #pragma unroll
            for (int h = 0; h < 2; ++h) {
                float v0, v1, v2, v3;
                upk2(acc[r][2 * h],     v0, v1);
                upk2(acc[r][2 * h + 1], v2, v3);
                float4 o;
                o.x = d * fmaxf(v0, 0.f);
                o.y = d * fmaxf(v1, 0.f);
                o.z = d * fmaxf(v2, 0.f);
                o.w = d * fmaxf(v3, 0.f);
                *reinterpret_cast<float4*>(ob + 128 * h) = o;
            }
        }
    }
}

extern "C" void kernel_launch(void* const* d_in, const int* in_sizes, int n_in,
                              void* d_out, int out_size) {
    (void)in_sizes; (void)n_in; (void)out_size;
    const float* adj = (const float*)d_in[0];
    const float* x   = (const float*)d_in[1];
    const float* W   = (const float*)d_in[2];
    float* out       = (float*)d_out;

    transpose_w<<<dim3(KD / 32, ED / 32), dim3(32, 8)>>>(W);

    cudaFuncSetAttribute(fused_gcn7,
                         cudaFuncAttributeMaxDynamicSharedMemorySize, SMEM_BYTES);
    fused_gcn7<<<NN / BR, NT, SMEM_BYTES>>>(adj, x, out);
}

// round 8
// speedup vs baseline: 2.6532x; 1.0490x over previous
#include <cuda_runtime.h>
#include <cstdint>
#include <cstddef>

#define NN 16384
#define KD 512
#define ED 256
#define BR 16                     // rows per tile
#define NTILE (NN / BR)           // 1024 tiles
#define GRID_P 304                // persistent CTAs (2 x 152 SMs)
#define NT 256                    // 4 stream warps + 4 GEMM warps
#define KCH 32                    // k per chunk
#define NCH (KD / KCH)            // 16 chunks per tile
#define CHUNK_BYTES (KCH * ED * 4)      // 32 KB
#define SMEM_BYTES (2 * CHUNK_BYTES)    // 64 KB ring

typedef unsigned long long ull;

__device__ float Wt_g[KD * ED];   // W transposed: Wt[k][e]

__device__ __forceinline__ ull pk2(float lo, float hi) {
    ull r; asm("mov.b64 %0, {%1, %2};" : "=l"(r) : "f"(lo), "f"(hi)); return r;
}
__device__ __forceinline__ void upk2(ull v, float& lo, float& hi) {
    asm("mov.b64 {%0, %1}, %2;" : "=f"(lo), "=f"(hi) : "l"(v));
}
__device__ __forceinline__ ull fma2(ull a, ull b, ull c) {
    ull d; asm("fma.rn.f32x2 %0, %1, %2, %3;" : "=l"(d) : "l"(a), "l"(b), "l"(c));
    return d;
}
__device__ __forceinline__ ull add2(ull a, ull b) {
    ull d; asm("add.rn.f32x2 %0, %1, %2;" : "=l"(d) : "l"(a), "l"(b));
    return d;
}
__device__ __forceinline__ uint32_t s2u(const void* p) {
    uint32_t a;
    asm("{ .reg .u64 t; cvta.to.shared.u64 t, %1; cvt.u32.u64 %0, t; }"
        : "=r"(a) : "l"(p));
    return a;
}
__device__ __forceinline__ void mbar_init(uint32_t mb, uint32_t cnt) {
    asm volatile("mbarrier.init.shared.b64 [%0], %1;" :: "r"(mb), "r"(cnt) : "memory");
}
__device__ __forceinline__ void mbar_expect(uint32_t mb, uint32_t bytes) {
    asm volatile("mbarrier.arrive.expect_tx.shared.b64 _, [%0], %1;"
                 :: "r"(mb), "r"(bytes) : "memory");
}
__device__ __forceinline__ void mbar_wait(uint32_t mb, uint32_t ph) {
    asm volatile(
        "{\n\t.reg .pred P;\n\t"
        "WL%=:\n\t"
        "mbarrier.try_wait.parity.acquire.cta.shared::cta.b64 P, [%0], %1, 0x989680;\n\t"
        "@P bra WD%=;\n\t"
        "bra WL%=;\n\t"
        "WD%=:\n\t}"
        :: "r"(mb), "r"(ph) : "memory");
}
__device__ __forceinline__ void bulk_g2s(uint32_t dst, const void* src,
                                         uint32_t bytes, uint32_t mb) {
    asm volatile(
        "cp.async.bulk.shared::cta.global.mbarrier::complete_tx::bytes [%0], [%1], %2, [%3];"
        :: "r"(dst), "l"(src), "r"(bytes), "r"(mb) : "memory");
}
__device__ __forceinline__ void bar_gemm() {   // GEMM warps only (id 1)
    asm volatile("bar.sync 1, 128;" ::: "memory");
}
__device__ __forceinline__ void bar_sync_id(int id) {
    asm volatile("bar.sync %0, 256;" :: "r"(id) : "memory");
}
__device__ __forceinline__ void bar_arrive_id(int id) {
    asm volatile("bar.arrive %0, 256;" :: "r"(id) : "memory");
}

// ---------------- W transpose: Wt[k][e] = W[e][k] -------------------------
__global__ void transpose_w(const float* __restrict__ W) {
    __shared__ float t[32][33];
    const int bk = blockIdx.x * 32;
    const int be = blockIdx.y * 32;
    const int tx = threadIdx.x, ty = threadIdx.y;   // 32 x 8
    #pragma unroll
    for (int j = 0; j < 32; j += 8)
        t[ty + j][tx] = W[(size_t)(be + ty + j) * KD + bk + tx];
    __syncthreads();
    #pragma unroll
    for (int j = 0; j < 32; j += 8)
        Wt_g[(size_t)(bk + ty + j) * ED + be + tx] = t[tx][ty + j];
}

// ---------------- persistent: stream warps + smem-staged GEMM warps -------
extern __shared__ float ws[];     // 2 x (32 x 256) floats

__global__ void __launch_bounds__(NT, 2)
fused_gcn8(const float* __restrict__ adj,
           const float* __restrict__ x,
           float* __restrict__ out)
{
    __shared__ float dsm[2][BR];
    __shared__ ull   mbar[2];

    const int tid  = threadIdx.x;
    const int wid  = tid >> 5;
    const int lane = tid & 31;
    const int bid  = blockIdx.x;

    const uint32_t wsb = s2u(ws);
    const uint32_t mb0 = s2u(mbar);

    if (tid == 128) {
        mbar_init(mb0, 1);
        mbar_init(mb0 + 8, 1);
    }
    __syncthreads();

    if (wid < 4) {
        // ===== STREAM WARPS: persistent tile loop =========================
        int ti = 0;
        #pragma unroll 1
        for (int t = bid; t < NTILE; t += GRID_P, ++ti) {
            const int b = ti & 1;
            if (ti >= 2) bar_sync_id(4 + b);    // dsm[b] consumed by GEMM
            const int r0 = t * BR;
            #pragma unroll 1
            for (int r = 0; r < 4; ++r) {
                const int row = 4 * wid + r;
                const float4* p = reinterpret_cast<const float4*>(
                    adj + (size_t)(r0 + row) * NN) + lane;
                ull sa = 0ULL, sb = 0ULL, sc = 0ULL, sd = 0ULL;
                #pragma unroll 1
                for (int j = 0; j < 128; j += 16) {
                    float4 v[16];
                    #pragma unroll
                    for (int u = 0; u < 16; ++u)
                        v[u] = __ldcs(p + (j + u) * 32);
                    #pragma unroll
                    for (int u = 0; u < 16; u += 4) {
                        sa = add2(sa, pk2(v[u + 0].x, v[u + 0].y));
                        sb = add2(sb, pk2(v[u + 0].z, v[u + 0].w));
                        sc = add2(sc, pk2(v[u + 1].x, v[u + 1].y));
                        sd = add2(sd, pk2(v[u + 1].z, v[u + 1].w));
                        sa = add2(sa, pk2(v[u + 2].x, v[u + 2].y));
                        sb = add2(sb, pk2(v[u + 2].z, v[u + 2].w));
                        sc = add2(sc, pk2(v[u + 3].x, v[u + 3].y));
                        sd = add2(sd, pk2(v[u + 3].z, v[u + 3].w));
                    }
                }
                sa = add2(sa, sb); sc = add2(sc, sd); sa = add2(sa, sc);
                float lo, hi; upk2(sa, lo, hi);
                float s = lo + hi;
                #pragma unroll
                for (int o = 16; o; o >>= 1)
                    s += __shfl_xor_sync(0xffffffffu, s, o);
                if (lane == 0) dsm[b][row] = 1.f / (s + 1.f) + 1.f;
            }
            __threadfence_block();
            bar_arrive_id(2 + b);               // dsm[b] ready
        }
    } else {
        // ===== GEMM WARPS: persistent tile loop, W ring rolls across tiles
        const int g = wid - 4;
        const int ntiles = (NTILE - bid + GRID_P - 1) / GRID_P;
        const int ncho = ntiles * NCH;          // total chunks this CTA

        if (tid == 128) {                       // prologue: chunks 0,1
            mbar_expect(mb0, CHUNK_BYTES);
            bulk_g2s(wsb, Wt_g, CHUNK_BYTES, mb0);
            mbar_expect(mb0 + 8, CHUNK_BYTES);
            bulk_g2s(wsb + CHUNK_BYTES, Wt_g + KCH * ED, CHUNK_BYTES, mb0 + 8);
        }

        int gc = 0, ti = 0;
        #pragma unroll 1
        for (int t = bid; t < NTILE; t += GRID_P, ++ti) {
            const int b2 = ti & 1;              // dsm buffer
            const float* xb = x + (size_t)(t * BR + 4 * g) * KD;

            ull acc[4][4];
            #pragma unroll
            for (int r = 0; r < 4; ++r)
                #pragma unroll
                for (int j = 0; j < 4; ++j) acc[r][j] = 0ULL;

            #pragma unroll 1
            for (int c = 0; c < NCH; ++c, ++gc) {
                const int wbuf = gc & 1;
                mbar_wait(mb0 + 8 * wbuf, (gc >> 1) & 1);

                const float* wsm = ws + wbuf * (KCH * ED) + 4 * lane;
                #pragma unroll
                for (int q = 0; q < KCH / 4; ++q) {
                    float a4[4][4];
                    #pragma unroll
                    for (int r = 0; r < 4; ++r) {   // warp-uniform broadcast
                        const float4 v = *reinterpret_cast<const float4*>(
                            xb + (size_t)r * KD + c * KCH + q * 4);
                        a4[r][0] = v.x; a4[r][1] = v.y;
                        a4[r][2] = v.z; a4[r][3] = v.w;
                    }
                    #pragma unroll
                    for (int u = 0; u < 4; ++u) {
                        const int kk = q * 4 + u;
                        const float4 blo = *reinterpret_cast<const float4*>(
                            wsm + kk * ED);
                        const float4 bhi = *reinterpret_cast<const float4*>(
                            wsm + kk * ED + 128);
                        ull b2r[4];
                        b2r[0] = pk2(blo.x, blo.y); b2r[1] = pk2(blo.z, blo.w);
                        b2r[2] = pk2(bhi.x, bhi.y); b2r[3] = pk2(bhi.z, bhi.w);
                        #pragma unroll
                        for (int r = 0; r < 4; ++r) {
                            const ull a2 = pk2(a4[r][u], a4[r][u]);
                            #pragma unroll
                            for (int j = 0; j < 4; ++j)
                                acc[r][j] = fma2(a2, b2r[j], acc[r][j]);
                        }
                    }
                }

                bar_gemm();                     // GEMM warps done with wbuf
                if (tid == 128 && gc + 2 < ncho) {
                    mbar_expect(mb0 + 8 * wbuf, CHUNK_BYTES);
                    bulk_g2s(wsb + wbuf * CHUNK_BYTES,
                             Wt_g + (size_t)((gc + 2) & (NCH - 1)) * KCH * ED,
                             CHUNK_BYTES, mb0 + 8 * wbuf);
                }
            }

            bar_sync_id(2 + b2);                // dsm[b2] ready
            #pragma unroll
            for (int r = 0; r < 4; ++r) {
                const float d = dsm[b2][4 * g + r];
                float* ob = out + (size_t)(t * BR + 4 * g + r) * ED + 4 * lane;
                #pragma unroll
                for (int h = 0; h < 2; ++h) {
                    float v0, v1, v2, v3;
                    upk2(acc[r][2 * h],     v0, v1);
                    upk2(acc[r][2 * h + 1], v2, v3);
                    float4 o;
                    o.x = d * fmaxf(v0, 0.f);
                    o.y = d * fmaxf(v1, 0.f);
                    o.z = d * fmaxf(v2, 0.f);
                    o.w = d * fmaxf(v3, 0.f);
                    *reinterpret_cast<float4*>(ob + 128 * h) = o;
                }
            }
            bar_arrive_id(4 + b2);              // dsm[b2] consumed
        }
    }
}

extern "C" void kernel_launch(void* const* d_in, const int* in_sizes, int n_in,
                              void* d_out, int out_size) {
    (void)in_sizes; (void)n_in; (void)out_size;
    const float* adj = (const float*)d_in[0];
    const float* x   = (const float*)d_in[1];
    const float* W   = (const float*)d_in[2];
    float* out       = (float*)d_out;

    transpose_w<<<dim3(KD / 32, ED / 32), dim3(32, 8)>>>(W);

    cudaFuncSetAttribute(fused_gcn8,
                         cudaFuncAttributeMaxDynamicSharedMemorySize, SMEM_BYTES);
    fused_gcn8<<<GRID_P, NT, SMEM_BYTES>>>(adj, x, out);
}